// round 3
// baseline (speedup 1.0000x reference)
#include <cuda_runtime.h>

// out[b, i] = x[b, i] * diagonal[i]
// x: [8192, 4096] f32, diagonal: [4096] f32, out: [8192, 4096] f32
//
// Column-stationary streaming kernel:
//  - each thread owns ONE float4 column, loads its diagonal float4 once,
//  - walks 32 rows, 8 rows in flight at a time (MLP=8).
//  - warp covers 32 consecutive float4 = 512B contiguous per row (coalesced).

static constexpr int SIZE     = 4096;
static constexpr int BATCH    = 8192;
static constexpr int SIZE_V4  = SIZE / 4;          // 1024 float4 per row
static constexpr int THREADS  = 256;               // covers 256 float4 = 1024 floats
static constexpr int COL_CHUNKS = SIZE_V4 / THREADS;   // 4
static constexpr int ROWS_PER_BLOCK = 32;
static constexpr int ROW_BLOCKS = BATCH / ROWS_PER_BLOCK;  // 256
static constexpr int UNROLL = 8;                   // rows in flight

__global__ __launch_bounds__(THREADS)
void diag_scale_kernel(const float4* __restrict__ x,
                       const float4* __restrict__ diag,
                       float4* __restrict__ out)
{
    // blockIdx.x = row_block * COL_CHUNKS + col_chunk
    const int col_chunk = blockIdx.x & (COL_CHUNKS - 1);
    const int row_block = blockIdx.x >> 2;   // / COL_CHUNKS

    const int c = col_chunk * THREADS + threadIdx.x;   // float4 column index
    const float4 dv = __ldg(&diag[c]);                 // loaded ONCE per thread

    long long idx = (long long)row_block * ROWS_PER_BLOCK * SIZE_V4 + c;

#pragma unroll
    for (int it = 0; it < ROWS_PER_BLOCK / UNROLL; it++) {
        float4 xv[UNROLL];
        // Front-batched independent loads: MLP = 8
#pragma unroll
        for (int k = 0; k < UNROLL; k++)
            xv[k] = __ldcs(&x[idx + (long long)k * SIZE_V4]);

#pragma unroll
        for (int k = 0; k < UNROLL; k++) {
            float4 ov;
            ov.x = xv[k].x * dv.x;
            ov.y = xv[k].y * dv.y;
            ov.z = xv[k].z * dv.z;
            ov.w = xv[k].w * dv.w;
            __stcs(&out[idx + (long long)k * SIZE_V4], ov);
        }
        idx += (long long)UNROLL * SIZE_V4;
    }
}

extern "C" void kernel_launch(void* const* d_in, const int* in_sizes, int n_in,
                              void* d_out, int out_size)
{
    const float4* x    = (const float4*)d_in[0];
    const float4* diag = (const float4*)d_in[1];
    float4*       out  = (float4*)d_out;

    const int blocks = ROW_BLOCKS * COL_CHUNKS;   // 1024
    diag_scale_kernel<<<blocks, THREADS>>>(x, diag, out);
}

// round 4
// speedup vs baseline: 1.0311x; 1.0311x over previous
#include <cuda_runtime.h>

// out[b, i] = x[b, i] * diagonal[i]
// x: [8192, 4096] f32, diagonal: [4096] f32, out: [8192, 4096] f32
//
// Hybrid layout: each thread owns ONE float4 column and 4 consecutive rows.
//  - diagonal loaded once per thread (removes 3 of 4 L1 diag loads vs R2)
//  - 4 front-batched x loads (MLP=4), streaming hints on both streams
//  - ~40 regs -> ~75% occupancy (vs R3's 66 regs / 33% occ failure)

static constexpr int SIZE     = 4096;
static constexpr int BATCH    = 8192;
static constexpr int SIZE_V4  = SIZE / 4;              // 1024 float4 per row
static constexpr int THREADS  = 256;
static constexpr int COL_CHUNKS = SIZE_V4 / THREADS;   // 4
static constexpr int ROWS_PER_THREAD = 4;
static constexpr int ROW_BLOCKS = BATCH / ROWS_PER_THREAD;  // 2048

__global__ __launch_bounds__(THREADS)
void diag_scale_kernel(const float4* __restrict__ x,
                       const float4* __restrict__ diag,
                       float4* __restrict__ out)
{
    // blockIdx.x = row_block * COL_CHUNKS + col_chunk
    const int col_chunk = blockIdx.x & (COL_CHUNKS - 1);
    const int row_block = blockIdx.x >> 2;            // / COL_CHUNKS

    const int c = col_chunk * THREADS + threadIdx.x;  // float4 column
    const float4 dv = __ldg(&diag[c]);                // ONE diag load per thread

    const long long base =
        (long long)row_block * ROWS_PER_THREAD * SIZE_V4 + c;

    // Front-batched independent loads: MLP = 4
    float4 xv[ROWS_PER_THREAD];
#pragma unroll
    for (int k = 0; k < ROWS_PER_THREAD; k++)
        xv[k] = __ldcs(&x[base + (long long)k * SIZE_V4]);

#pragma unroll
    for (int k = 0; k < ROWS_PER_THREAD; k++) {
        float4 ov;
        ov.x = xv[k].x * dv.x;
        ov.y = xv[k].y * dv.y;
        ov.z = xv[k].z * dv.z;
        ov.w = xv[k].w * dv.w;
        __stcs(&out[base + (long long)k * SIZE_V4], ov);
    }
}

extern "C" void kernel_launch(void* const* d_in, const int* in_sizes, int n_in,
                              void* d_out, int out_size)
{
    const float4* x    = (const float4*)d_in[0];
    const float4* diag = (const float4*)d_in[1];
    float4*       out  = (float4*)d_out;

    const int blocks = ROW_BLOCKS * COL_CHUNKS;   // 8192
    diag_scale_kernel<<<blocks, THREADS>>>(x, diag, out);
}

// round 5
// speedup vs baseline: 1.0471x; 1.0154x over previous
#include <cuda_runtime.h>

// out[b, i] = x[b, i] * diagonal[i]
// x: [8192, 4096] f32, diagonal: [4096] f32, out: [8192, 4096] f32
//
// Blackwell 256-bit global accesses (ld/st.global.v8.f32) to halve L1tex
// wavefronts per byte. 2x v8 per thread, front-batched (MLP=2x256b).

static constexpr int SIZE    = 4096;
static constexpr int BATCH   = 8192;
static constexpr int SIZE_V8 = SIZE / 8;                     // 512 v8 per row
static constexpr long long TOTAL_V8 = (long long)SIZE * BATCH / 8;  // 4,194,304
static constexpr int THREADS = 256;
static constexpr int VPT     = 2;                            // v8 per thread

struct __align__(32) f8 { float v[8]; };

__device__ __forceinline__ f8 ldg256_cs(const f8* p) {
    f8 r;
    asm volatile("ld.global.cs.nc.v8.f32 {%0,%1,%2,%3,%4,%5,%6,%7}, [%8];"
                 : "=f"(r.v[0]), "=f"(r.v[1]), "=f"(r.v[2]), "=f"(r.v[3]),
                   "=f"(r.v[4]), "=f"(r.v[5]), "=f"(r.v[6]), "=f"(r.v[7])
                 : "l"(p));
    return r;
}

__device__ __forceinline__ void stg256_cs(f8* p, const f8& r) {
    asm volatile("st.global.cs.v8.f32 [%0], {%1,%2,%3,%4,%5,%6,%7,%8};"
                 :: "l"(p),
                    "f"(r.v[0]), "f"(r.v[1]), "f"(r.v[2]), "f"(r.v[3]),
                    "f"(r.v[4]), "f"(r.v[5]), "f"(r.v[6]), "f"(r.v[7])
                 : "memory");
}

__global__ __launch_bounds__(THREADS)
void diag_scale_kernel(const f8* __restrict__ x,
                       const f8* __restrict__ diag,
                       f8* __restrict__ out)
{
    // Each block owns a contiguous chunk of THREADS*VPT v8s.
    const long long base = (long long)blockIdx.x * (THREADS * VPT) + threadIdx.x;

    // Front-batched independent 256-bit loads.
    f8 xv[VPT];
#pragma unroll
    for (int k = 0; k < VPT; k++)
        xv[k] = ldg256_cs(&x[base + (long long)k * THREADS]);

#pragma unroll
    for (int k = 0; k < VPT; k++) {
        const long long i = base + (long long)k * THREADS;
        const int c = (int)(i & (SIZE_V8 - 1));        // v8 column in row
        // diagonal: 16 KiB, L1-resident; two 128-bit cached loads
        const float4 d0 = __ldg(&((const float4*)diag)[2 * c + 0]);
        const float4 d1 = __ldg(&((const float4*)diag)[2 * c + 1]);

        f8 ov;
        ov.v[0] = xv[k].v[0] * d0.x;
        ov.v[1] = xv[k].v[1] * d0.y;
        ov.v[2] = xv[k].v[2] * d0.z;
        ov.v[3] = xv[k].v[3] * d0.w;
        ov.v[4] = xv[k].v[4] * d1.x;
        ov.v[5] = xv[k].v[5] * d1.y;
        ov.v[6] = xv[k].v[6] * d1.z;
        ov.v[7] = xv[k].v[7] * d1.w;
        stg256_cs(&out[i], ov);
    }
}

extern "C" void kernel_launch(void* const* d_in, const int* in_sizes, int n_in,
                              void* d_out, int out_size)
{
    const f8* x    = (const f8*)d_in[0];
    const f8* diag = (const f8*)d_in[1];
    f8*       out  = (f8*)d_out;

    const int blocks = (int)(TOTAL_V8 / (THREADS * VPT));   // 8192, exact
    diag_scale_kernel<<<blocks, THREADS>>>(x, diag, out);
}